// round 1
// baseline (speedup 1.0000x reference)
#include <cuda_runtime.h>

#define BDIM 256
#define C 256
#define HW (56*56)
#define NPLANE (32*256)

// scratch (allocation-free rule: __device__ globals)
__device__ float g_pooled[32 * 256];        // [B, C]
__device__ float g_kern[32 * 256 * 9];      // [B, C*9] == [plane, 9]

// ---------------- kernel 1: global average pool ----------------
__global__ void pool_kernel(const float* __restrict__ x) {
    const int plane = blockIdx.x;
    const float4* xp = reinterpret_cast<const float4*>(x + (size_t)plane * HW);
    float s = 0.f;
    #pragma unroll 4
    for (int i = threadIdx.x; i < HW / 4; i += BDIM) {
        float4 v = xp[i];
        s += (v.x + v.y) + (v.z + v.w);
    }
    #pragma unroll
    for (int o = 16; o; o >>= 1) s += __shfl_xor_sync(0xffffffffu, s, o);
    __shared__ float sh[8];
    if ((threadIdx.x & 31) == 0) sh[threadIdx.x >> 5] = s;
    __syncthreads();
    if (threadIdx.x < 32) {
        s = (threadIdx.x < 8) ? sh[threadIdx.x] : 0.f;
        #pragma unroll
        for (int o = 4; o; o >>= 1) s += __shfl_xor_sync(0xffffffffu, s, o);
        if (threadIdx.x == 0) g_pooled[plane] = s * (1.0f / HW);
    }
}

// ---------------- kernel 2: kern = relu(pooled @ Wk^T + bk) ----------------
// Wk: [2304, 256] row-major. One warp per output row o; lanes walk c (coalesced).
__global__ void kgen_kernel(const float* __restrict__ Wk, const float* __restrict__ bk) {
    __shared__ float psh[32 * 256];
    for (int i = threadIdx.x; i < 32 * 256; i += BDIM) psh[i] = g_pooled[i];
    __syncthreads();

    const int warp = threadIdx.x >> 5;
    const int lane = threadIdx.x & 31;
    const int o = blockIdx.x * 8 + warp;   // 288 blocks * 8 warps = 2304

    float w[8];
    const float* wr = Wk + (size_t)o * 256;
    #pragma unroll
    for (int i = 0; i < 8; i++) w[i] = wr[lane + 32 * i];
    const float bias = bk[o];

    for (int b = 0; b < 32; b++) {
        const float* pr = psh + b * 256;
        float p = 0.f;
        #pragma unroll
        for (int i = 0; i < 8; i++) p = fmaf(w[i], pr[lane + 32 * i], p);
        #pragma unroll
        for (int off = 16; off; off >>= 1) p += __shfl_xor_sync(0xffffffffu, p, off);
        if (lane == 0) g_kern[b * 2304 + o] = fmaxf(p + bias, 0.f);
    }
}

// ---------------- kernel 3: per-plane depthwise 3x3 conv, pad 1 ----------------
__global__ void dconv_kernel(const float* __restrict__ x, float* __restrict__ out) {
    const int plane = blockIdx.x;              // b*C + c
    __shared__ float s[58 * 58];
    __shared__ float kf[9];

    const float* xp = x + (size_t)plane * HW;
    if (threadIdx.x < 9) kf[threadIdx.x] = g_kern[plane * 9 + threadIdx.x];

    // load 58x58 halo tile (zero padded)
    for (int i = threadIdx.x; i < 58 * 58; i += BDIM) {
        const int sy = i / 58, sx = i - sy * 58;
        const int gy = sy - 1, gx = sx - 1;
        float v = 0.f;
        if ((unsigned)gy < 56u && (unsigned)gx < 56u) v = xp[gy * 56 + gx];
        s[i] = v;
    }
    __syncthreads();

    const float k0 = kf[0], k1 = kf[1], k2 = kf[2];
    const float k3 = kf[3], k4 = kf[4], k5 = kf[5];
    const float k6 = kf[6], k7 = kf[7], k8 = kf[8];

    float* op = out + (size_t)plane * HW;
    for (int p = threadIdx.x; p < HW; p += BDIM) {
        const int y = p / 56, xq = p - y * 56;
        const float* r = s + y * 58 + xq;
        float acc;
        acc  = k0 * r[0];
        acc  = fmaf(k1, r[1],   acc);
        acc  = fmaf(k2, r[2],   acc);
        acc  = fmaf(k3, r[58],  acc);
        acc  = fmaf(k4, r[59],  acc);
        acc  = fmaf(k5, r[60],  acc);
        acc  = fmaf(k6, r[116], acc);
        acc  = fmaf(k7, r[117], acc);
        acc  = fmaf(k8, r[118], acc);
        op[p] = acc;
    }
}

extern "C" void kernel_launch(void* const* d_in, const int* in_sizes, int n_in,
                              void* d_out, int out_size) {
    const float* x  = (const float*)d_in[0];   // [32,256,56,56]
    const float* Wk = (const float*)d_in[1];   // [2304,256]
    const float* bk = (const float*)d_in[2];   // [2304]
    float* out = (float*)d_out;

    pool_kernel<<<NPLANE, BDIM>>>(x);
    kgen_kernel<<<288, BDIM>>>(Wk, bk);
    dconv_kernel<<<NPLANE, BDIM>>>(x, out);
}

// round 2
// speedup vs baseline: 1.5472x; 1.5472x over previous
#include <cuda_runtime.h>

#define BDIM 256
#define HW (56*56)
#define NPLANE (32*256)

__device__ float g_pooled[32 * 256];        // [B, C]
__device__ float g_kern[32 * 256 * 9];      // [plane, 9]

// ---------------- kernel 1: global average pool (4 planes / block) ----------------
__global__ void pool_kernel(const float* __restrict__ x) {
    const int plane0 = blockIdx.x * 4;
    const float4* xp = reinterpret_cast<const float4*>(x + (size_t)plane0 * HW);
    float s0 = 0.f, s1 = 0.f, s2 = 0.f, s3 = 0.f;
    for (int i = threadIdx.x; i < 784; i += BDIM) {
        float4 a = xp[i];
        float4 b = xp[i + 784];
        float4 c = xp[i + 1568];
        float4 d = xp[i + 2352];
        s0 += (a.x + a.y) + (a.z + a.w);
        s1 += (b.x + b.y) + (b.z + b.w);
        s2 += (c.x + c.y) + (c.z + c.w);
        s3 += (d.x + d.y) + (d.z + d.w);
    }
    #pragma unroll
    for (int o = 16; o; o >>= 1) {
        s0 += __shfl_xor_sync(0xffffffffu, s0, o);
        s1 += __shfl_xor_sync(0xffffffffu, s1, o);
        s2 += __shfl_xor_sync(0xffffffffu, s2, o);
        s3 += __shfl_xor_sync(0xffffffffu, s3, o);
    }
    __shared__ float sh[8][4];
    if ((threadIdx.x & 31) == 0) {
        const int w = threadIdx.x >> 5;
        sh[w][0] = s0; sh[w][1] = s1; sh[w][2] = s2; sh[w][3] = s3;
    }
    __syncthreads();
    if (threadIdx.x < 32) {
        const int pl = threadIdx.x & 3;      // lanes 0..31 -> (warp w = lane>>2, pl = lane&3)
        const int w  = threadIdx.x >> 2;
        float v = (w < 8) ? sh[w][pl] : 0.f;
        // reduce over the 8 warps: lanes with same pl are strided by 4
        v += __shfl_xor_sync(0xffffffffu, v, 16);
        v += __shfl_xor_sync(0xffffffffu, v, 8);
        v += __shfl_xor_sync(0xffffffffu, v, 4);
        if (w == 0) g_pooled[plane0 + pl] = v * (1.0f / HW);
    }
}

// ---------------- kernel 2: kern = relu(pooled @ Wk^T + bk) ----------------
__global__ void kgen_kernel(const float* __restrict__ Wk, const float* __restrict__ bk) {
    __shared__ float psh[32 * 256];
    for (int i = threadIdx.x; i < 32 * 256; i += BDIM) psh[i] = g_pooled[i];
    __syncthreads();

    const int warp = threadIdx.x >> 5;
    const int lane = threadIdx.x & 31;
    const int o = blockIdx.x * 8 + warp;   // 288 blocks * 8 warps = 2304

    float w[8];
    const float* wr = Wk + (size_t)o * 256;
    #pragma unroll
    for (int i = 0; i < 8; i++) w[i] = wr[lane + 32 * i];
    const float bias = bk[o];

    for (int b = 0; b < 32; b++) {
        const float* pr = psh + b * 256;
        float p = 0.f;
        #pragma unroll
        for (int i = 0; i < 8; i++) p = fmaf(w[i], pr[lane + 32 * i], p);
        #pragma unroll
        for (int off = 16; off; off >>= 1) p += __shfl_xor_sync(0xffffffffu, p, off);
        if (lane == 0) g_kern[b * 2304 + o] = fmaxf(p + bias, 0.f);
    }
}

// ---------------- kernel 3: depthwise 3x3, rolling register window ----------------
// smem tile: 58 rows x 56 cols. smem row (y+1) holds global row y; rows 0,57 = zero.
// Column halo handled by predicated edge loads (no padded columns -> float4 stores stay aligned).
__global__ void dconv_kernel(const float* __restrict__ x, float* __restrict__ out) {
    const int plane = blockIdx.x;
    __shared__ float s[58 * 56];
    __shared__ float kf[9];

    const int tid = threadIdx.x;
    if (tid < 9) kf[tid] = g_kern[plane * 9 + tid];

    const float4* xp = reinterpret_cast<const float4*>(x + (size_t)plane * HW);
    float4* sp = reinterpret_cast<float4*>(s + 56);          // smem row 1
    for (int i = tid; i < 784; i += BDIM) sp[i] = xp[i];
    // zero halo rows 0 and 57 (14 float4 each)
    if (tid < 14)      reinterpret_cast<float4*>(s)[tid] = make_float4(0.f, 0.f, 0.f, 0.f);
    else if (tid < 28) reinterpret_cast<float4*>(s)[57 * 14 + (tid - 14)] = make_float4(0.f, 0.f, 0.f, 0.f);
    __syncthreads();

    if (tid >= 224) return;                 // no further __syncthreads below
    const int xc = tid % 56;
    const int y0 = (tid / 56) * 14;         // 4 row-groups of 14

    const bool lok = xc > 0;
    const bool rok = xc < 55;

    const float k0 = kf[0], k1 = kf[1], k2 = kf[2];
    const float k3 = kf[3], k4 = kf[4], k5 = kf[5];
    const float k6 = kf[6], k7 = kf[7], k8 = kf[8];

    // rolling 3-row window; smem row index for global row y is (y+1)
    const float* r0 = s + y0 * 56 + xc;            // global row y0-1
    const float* r1 = r0 + 56;                     // global row y0
    float u1 = r0[0], u0 = lok ? r0[-1] : 0.f, u2 = rok ? r0[1] : 0.f;
    float v1 = r1[0], v0 = lok ? r1[-1] : 0.f, v2 = rok ? r1[1] : 0.f;

    float* op = out + (size_t)plane * HW + y0 * 56 + xc;

    #pragma unroll
    for (int r = 0; r < 14; r++) {
        const float* rp = s + (y0 + r + 2) * 56 + xc;   // global row y0+r+1
        const float w1 = rp[0];
        const float w0 = lok ? rp[-1] : 0.f;
        const float w2 = rok ? rp[1] : 0.f;

        float acc = k0 * u0;
        acc = fmaf(k1, u1, acc);
        acc = fmaf(k2, u2, acc);
        acc = fmaf(k3, v0, acc);
        acc = fmaf(k4, v1, acc);
        acc = fmaf(k5, v2, acc);
        acc = fmaf(k6, w0, acc);
        acc = fmaf(k7, w1, acc);
        acc = fmaf(k8, w2, acc);
        __stcs(op + r * 56, acc);                        // streaming store: keep x in L2

        u0 = v0; u1 = v1; u2 = v2;
        v0 = w0; v1 = w1; v2 = w2;
    }
}

extern "C" void kernel_launch(void* const* d_in, const int* in_sizes, int n_in,
                              void* d_out, int out_size) {
    const float* x  = (const float*)d_in[0];   // [32,256,56,56]
    const float* Wk = (const float*)d_in[1];   // [2304,256]
    const float* bk = (const float*)d_in[2];   // [2304]
    float* out = (float*)d_out;

    pool_kernel<<<NPLANE / 4, BDIM>>>(x);
    kgen_kernel<<<288, BDIM>>>(Wk, bk);
    dconv_kernel<<<NPLANE, BDIM>>>(x, out);
}